// round 2
// baseline (speedup 1.0000x reference)
#include <cuda_runtime.h>
#include <math.h>

#define SEQ   2048
#define DM    2048
#define NH    16
#define HD    128
#define NB    2
#define MT    (NB*SEQ)          // 4096 rows

// ---------------- scratch (static __device__, no allocs) ----------------
__device__ float g_q  [NB*NH*SEQ*HD];   // [b][h][s][d]
__device__ float g_k  [NB*NH*SEQ*HD];
__device__ float g_v  [NB*NH*SEQ*HD];
__device__ float g_ctx[(size_t)MT*DM];  // [b*s][D]
__device__ float g_cos[SEQ*64];
__device__ float g_sin[SEQ*64];

// ---------------- GEMM: C = A[M,K] * W[N,K]^T ----------------
// BM=BN=128, BK=8, 256 threads, 8x8 microtile (split 4+4 to avoid conflicts).
// mode 0: A=x param, W selected by blockIdx.z (Wq/Wk/Wv), C -> g_q/g_k/g_v in
//         head layout [b][h][s][d].
// mode 1: A=g_ctx, W=W0 (Wo), C=out param, plain [M,N] layout.
__global__ __launch_bounds__(256) void gemm_kernel(
    const float* __restrict__ Ap, const float* __restrict__ W0,
    const float* __restrict__ W1, const float* __restrict__ W2,
    float* __restrict__ outp, int mode)
{
    __shared__ float As[8][128];
    __shared__ float Bs[8][128];

    const float* A;
    const float* W;
    float* C;
    int z = blockIdx.z;
    if (mode == 0) {
        A = Ap;
        W = (z == 0) ? W0 : (z == 1) ? W1 : W2;
        C = (z == 0) ? g_q : (z == 1) ? g_k : g_v;
    } else {
        A = g_ctx; W = W0; C = outp;
    }

    int tid  = threadIdx.x;
    int m0   = blockIdx.y * 128;
    int n0   = blockIdx.x * 128;
    int lrow = tid >> 1;           // 0..127
    int lcol = (tid & 1) << 2;     // 0 or 4
    int tx   = tid & 15, ty = tid >> 4;

    float acc[8][8];
#pragma unroll
    for (int i = 0; i < 8; i++)
#pragma unroll
        for (int j = 0; j < 8; j++) acc[i][j] = 0.f;

    const float* Aptr = A + (size_t)(m0 + lrow) * DM + lcol;
    const float* Wptr = W + (size_t)(n0 + lrow) * DM + lcol;

    for (int k0 = 0; k0 < DM; k0 += 8) {
        float4 av = *(const float4*)(Aptr + k0);
        float4 bv = *(const float4*)(Wptr + k0);
        __syncthreads();
        As[lcol+0][lrow] = av.x; As[lcol+1][lrow] = av.y;
        As[lcol+2][lrow] = av.z; As[lcol+3][lrow] = av.w;
        Bs[lcol+0][lrow] = bv.x; Bs[lcol+1][lrow] = bv.y;
        Bs[lcol+2][lrow] = bv.z; Bs[lcol+3][lrow] = bv.w;
        __syncthreads();
#pragma unroll
        for (int kk = 0; kk < 8; kk++) {
            float ar[8], br[8];
            *(float4*)(ar)     = *(const float4*)&As[kk][ty*4];
            *(float4*)(ar + 4) = *(const float4*)&As[kk][64 + ty*4];
            *(float4*)(br)     = *(const float4*)&Bs[kk][tx*4];
            *(float4*)(br + 4) = *(const float4*)&Bs[kk][64 + tx*4];
#pragma unroll
            for (int i = 0; i < 8; i++)
#pragma unroll
                for (int j = 0; j < 8; j++) acc[i][j] += ar[i] * br[j];
        }
    }

#pragma unroll
    for (int i = 0; i < 8; i++) {
        int m = m0 + ((i < 4) ? (ty*4 + i) : (64 + ty*4 + (i - 4)));
#pragma unroll
        for (int j = 0; j < 8; j++) {
            int n = n0 + ((j < 4) ? (tx*4 + j) : (64 + tx*4 + (j - 4)));
            float v = acc[i][j];
            if (mode == 0) {
                int b = m >> 11, s = m & (SEQ - 1);
                int h = n >> 7,  d = n & (HD - 1);
                C[(((size_t)(b * NH + h)) * SEQ + s) * HD + d] = v;
            } else {
                C[(size_t)m * DM + n] = v;
            }
        }
    }
}

// ---------------- RoPE tables ----------------
__global__ void rope_table_kernel() {
    int idx = blockIdx.x * 256 + threadIdx.x;   // SEQ*64
    if (idx >= SEQ * 64) return;
    int s = idx >> 6, i = idx & 63;
    float inv = (float)pow(10000.0, -(double)(2 * i) / 128.0);
    float ang = (float)s * inv;
    g_cos[idx] = cosf(ang);
    g_sin[idx] = sinf(ang);
}

// ---------------- RoPE apply (in place on g_q / g_k) ----------------
__global__ void rope_apply_kernel() {
    int idx = blockIdx.x * 256 + threadIdx.x;   // 32*2048*64 elements
    float* t = blockIdx.y ? g_k : g_q;
    int i = idx & 63;
    int s = (idx >> 6) & (SEQ - 1);
    float c  = g_cos[s * 64 + i];
    float sn = g_sin[s * 64 + i];
    size_t base = ((size_t)(idx >> 6)) * HD;    // (bh*SEQ + s)*128
    float a = t[base + i];
    float b = t[base + 64 + i];
    t[base + i]      = a * c - b * sn;
    t[base + 64 + i] = b * c + a * sn;
}

// ---------------- flash attention (fp32, causal, online softmax) ----------------
// One CTA per (q-block of 64 rows, b*h). BN=64 kv cols/iter, 256 threads.
#define FBM 64
#define FBN 64
#define FLASH_SMEM ((128*64 + 128*64 + 64*65 + 3*64) * 4)

__global__ __launch_bounds__(256) void flash_kernel()
{
    extern __shared__ float sm[];
    float* Qs    = sm;                  // [128][64]  (d-major, Q pre-scaled)
    float* KVs   = sm + 128 * 64;       // K: [128][64] then V: [64][128]
    float* Ps    = KVs + 128 * 64;      // [64][65]   (padded stride)
    float* rowm  = Ps + 64 * 65;
    float* rowl  = rowm + 64;
    float* rowsc = rowl + 64;

    int tid = threadIdx.x;
    int qb  = blockIdx.x;               // 0..31
    int bh  = blockIdx.y;               // 0..31

    const float* Qg = g_q + (size_t)bh * SEQ * HD;
    const float* Kg = g_k + (size_t)bh * SEQ * HD;
    const float* Vg = g_v + (size_t)bh * SEQ * HD;

    int lr  = tid >> 2;                 // 0..63 row within tile
    int lcb = (tid & 3) * 32;           // d-chunk base

    const float qscale = 0.08838834764831845f;  // 1/sqrt(128)
#pragma unroll
    for (int c = 0; c < 32; c += 4) {
        float4 v = *(const float4*)(Qg + (size_t)(qb * FBM + lr) * HD + lcb + c);
        Qs[(lcb + c + 0) * 64 + lr] = v.x * qscale;
        Qs[(lcb + c + 1) * 64 + lr] = v.y * qscale;
        Qs[(lcb + c + 2) * 64 + lr] = v.z * qscale;
        Qs[(lcb + c + 3) * 64 + lr] = v.w * qscale;
    }
    if (tid < 64) { rowm[tid] = -1e30f; rowl[tid] = 0.f; }

    int tx = tid & 15, ty = tid >> 4;
    float O[4][8];
#pragma unroll
    for (int i = 0; i < 4; i++)
#pragma unroll
        for (int j = 0; j < 8; j++) O[i][j] = 0.f;

    for (int kb = 0; kb <= qb; kb++) {
        __syncthreads();   // prev PV done with KVs; first iter: Q/rowm visible
        // load K transposed into KVs
#pragma unroll
        for (int c = 0; c < 32; c += 4) {
            float4 v = *(const float4*)(Kg + (size_t)(kb * FBN + lr) * HD + lcb + c);
            KVs[(lcb + c + 0) * 64 + lr] = v.x;
            KVs[(lcb + c + 1) * 64 + lr] = v.y;
            KVs[(lcb + c + 2) * 64 + lr] = v.z;
            KVs[(lcb + c + 3) * 64 + lr] = v.w;
        }
        __syncthreads();

        // S = Qs^T * Ks (64x64), 4x4 microtile per thread
        float s[4][4];
#pragma unroll
        for (int i = 0; i < 4; i++)
#pragma unroll
            for (int j = 0; j < 4; j++) s[i][j] = 0.f;
#pragma unroll 4
        for (int d = 0; d < HD; d++) {
            float4 q4 = *(const float4*)&Qs [d * 64 + ty * 4];
            float4 k4 = *(const float4*)&KVs[d * 64 + tx * 4];
            float qv[4] = {q4.x, q4.y, q4.z, q4.w};
            float kv[4] = {k4.x, k4.y, k4.z, k4.w};
#pragma unroll
            for (int i = 0; i < 4; i++)
#pragma unroll
                for (int j = 0; j < 4; j++) s[i][j] += qv[i] * kv[j];
        }
        if (kb == qb) {  // causal mask on diagonal block
#pragma unroll
            for (int i = 0; i < 4; i++)
#pragma unroll
                for (int j = 0; j < 4; j++)
                    if ((tx * 4 + j) > (ty * 4 + i)) s[i][j] = -1e30f;
        }
#pragma unroll
        for (int i = 0; i < 4; i++)
#pragma unroll
            for (int j = 0; j < 4; j++)
                Ps[(ty * 4 + i) * 65 + tx * 4 + j] = s[i][j];
        __syncthreads();

        // online softmax, one thread per row
        if (tid < 64) {
            int r = tid;
            float mold = rowm[r];
            float mx = mold;
#pragma unroll 8
            for (int c = 0; c < 64; c++) mx = fmaxf(mx, Ps[r * 65 + c]);
            float sc = __expf(mold - mx);
            float sum = 0.f;
#pragma unroll 8
            for (int c = 0; c < 64; c++) {
                float p = __expf(Ps[r * 65 + c] - mx);
                Ps[r * 65 + c] = p;
                sum += p;
            }
            rowl[r]  = rowl[r] * sc + sum;
            rowm[r]  = mx;
            rowsc[r] = sc;
        }
        __syncthreads();

        // rescale O; load V (natural layout) into KVs
#pragma unroll
        for (int i = 0; i < 4; i++) {
            float sc = rowsc[ty * 4 + i];
#pragma unroll
            for (int j = 0; j < 8; j++) O[i][j] *= sc;
        }
#pragma unroll
        for (int c = 0; c < 32; c += 4) {
            float4 v = *(const float4*)(Vg + (size_t)(kb * FBN + lr) * HD + lcb + c);
            *(float4*)&KVs[lr * HD + lcb + c] = v;
        }
        __syncthreads();

        // O += P * V, 4x8 microtile
#pragma unroll 2
        for (int j = 0; j < FBN; j++) {
            float4 v0 = *(const float4*)&KVs[j * HD + tx * 8];
            float4 v1 = *(const float4*)&KVs[j * HD + tx * 8 + 4];
            float vv[8] = {v0.x, v0.y, v0.z, v0.w, v1.x, v1.y, v1.z, v1.w};
#pragma unroll
            for (int i = 0; i < 4; i++) {
                float p = Ps[(ty * 4 + i) * 65 + j];
#pragma unroll
                for (int c = 0; c < 8; c++) O[i][c] += p * vv[c];
            }
        }
    }

    // epilogue: normalize and write ctx in [b][s][h*128+d] layout
    int b = bh >> 4, h = bh & 15;
#pragma unroll
    for (int i = 0; i < 4; i++) {
        int r = ty * 4 + i;
        float inv = 1.0f / rowl[r];
        int srow = qb * FBM + r;
        float* dst = g_ctx + ((size_t)(b * SEQ + srow)) * DM + h * HD + tx * 8;
#pragma unroll
        for (int c = 0; c < 8; c++) dst[c] = O[i][c] * inv;
    }
}

// ---------------- launcher ----------------
extern "C" void kernel_launch(void* const* d_in, const int* in_sizes, int n_in,
                              void* d_out, int out_size)
{
    const float* x  = (const float*)d_in[0];
    const float* Wq = (const float*)d_in[1];
    const float* Wk = (const float*)d_in[2];
    const float* Wv = (const float*)d_in[3];
    const float* Wo = (const float*)d_in[4];
    float* out = (float*)d_out;

    cudaFuncSetAttribute(flash_kernel,
                         cudaFuncAttributeMaxDynamicSharedMemorySize, FLASH_SMEM);

    // Q/K/V projections -> head layout
    gemm_kernel<<<dim3(DM/128, MT/128, 3), 256>>>(x, Wq, Wk, Wv, nullptr, 0);
    // RoPE tables + apply to Q and K
    rope_table_kernel<<<(SEQ*64)/256, 256>>>();
    rope_apply_kernel<<<dim3((NB*NH*SEQ*64)/256, 2), 256>>>();
    // causal flash attention -> g_ctx
    flash_kernel<<<dim3(SEQ/FBM, NB*NH), 256, FLASH_SMEM>>>();
    // output projection
    gemm_kernel<<<dim3(DM/128, MT/128, 1), 256>>>(nullptr, Wo, nullptr, nullptr, out, 1);
}

// round 3
// speedup vs baseline: 1.3672x; 1.3672x over previous
#include <cuda_runtime.h>
#include <math.h>

#define SEQ   2048
#define DM    2048
#define NH    16
#define HD    128
#define NB    2
#define MT    (NB*SEQ)          // 4096 rows

// ---------------- scratch (static __device__, no allocs) ----------------
__device__ float g_q  [NB*NH*SEQ*HD];   // [b][h][s][d]
__device__ float g_k  [NB*NH*SEQ*HD];
__device__ float g_v  [NB*NH*SEQ*HD];
__device__ float g_ctx[(size_t)MT*DM];  // [b*s][D]
__device__ float g_cos[SEQ*64];
__device__ float g_sin[SEQ*64];

// ---------------- helpers ----------------
__device__ __forceinline__ unsigned f2tf32(float x) {
    unsigned r;
    asm("cvt.rna.tf32.f32 %0, %1;" : "=r"(r) : "f"(x));
    return r;
}

// ---------------- TF32 tensor-core GEMM: C = A[M,K] * W[N,K]^T ----------------
// BM=BN=128, BK=16, 128 threads (4 warps, 2x2), warp tile 64x64 via
// mma.sync.m16n8k8.tf32. Double-buffered smem, stride 20 (conflict-free for
// the fragment pattern), register-prefetch pipeline, 1 sync/iter.
// mode 0: A=Ap, W chosen by blockIdx.z (Wq/Wk/Wv), C -> g_q/g_k/g_v head layout.
// mode 1: A=g_ctx, W=W0 (Wo), C=outp, [M,N] layout.
#define KSTRIDE 20

__global__ __launch_bounds__(128) void gemm_tc_kernel(
    const float* __restrict__ Ap, const float* __restrict__ W0,
    const float* __restrict__ W1, const float* __restrict__ W2,
    float* __restrict__ outp, int mode)
{
    __shared__ float As[2][128][KSTRIDE];
    __shared__ float Bs[2][128][KSTRIDE];

    const float* A;
    const float* W;
    float* C;
    int z = blockIdx.z;
    if (mode == 0) {
        A = Ap;
        W = (z == 0) ? W0 : (z == 1) ? W1 : W2;
        C = (z == 0) ? g_q : (z == 1) ? g_k : g_v;
    } else {
        A = g_ctx; W = W0; C = outp;
    }

    int tid   = threadIdx.x;
    int lane  = tid & 31;
    int warp  = tid >> 5;
    int warpM = warp >> 1;       // 0..1
    int warpN = warp & 1;        // 0..1
    int m0    = blockIdx.y * 128;
    int n0    = blockIdx.x * 128;

    const float* Ag = A + (size_t)(m0 + tid) * DM;   // this thread's A row
    const float* Wg = W + (size_t)(n0 + tid) * DM;   // this thread's W row

    float acc[4][8][4];
#pragma unroll
    for (int i = 0; i < 4; i++)
#pragma unroll
        for (int j = 0; j < 8; j++)
#pragma unroll
            for (int c = 0; c < 4; c++) acc[i][j][c] = 0.f;

    float4 ra[4], rb[4];
    // prefetch tile 0
#pragma unroll
    for (int c = 0; c < 4; c++) {
        ra[c] = *(const float4*)(Ag + c * 4);
        rb[c] = *(const float4*)(Wg + c * 4);
    }
    // store tile 0 (tf32-rounded)
    {
        float* ar = &As[0][tid][0];
        float* br = &Bs[0][tid][0];
#pragma unroll
        for (int c = 0; c < 4; c++) {
            ar[c*4+0] = __uint_as_float(f2tf32(ra[c].x));
            ar[c*4+1] = __uint_as_float(f2tf32(ra[c].y));
            ar[c*4+2] = __uint_as_float(f2tf32(ra[c].z));
            ar[c*4+3] = __uint_as_float(f2tf32(ra[c].w));
            br[c*4+0] = __uint_as_float(f2tf32(rb[c].x));
            br[c*4+1] = __uint_as_float(f2tf32(rb[c].y));
            br[c*4+2] = __uint_as_float(f2tf32(rb[c].z));
            br[c*4+3] = __uint_as_float(f2tf32(rb[c].w));
        }
    }
    __syncthreads();

    const int NKT = DM / 16;   // 128 k-tiles
    for (int kt = 0; kt < NKT; kt++) {
        int cur = kt & 1;
        // prefetch next tile into registers (latency hidden behind MMAs)
        if (kt < NKT - 1) {
            const float* ap = Ag + (kt + 1) * 16;
            const float* wp = Wg + (kt + 1) * 16;
#pragma unroll
            for (int c = 0; c < 4; c++) {
                ra[c] = *(const float4*)(ap + c * 4);
                rb[c] = *(const float4*)(wp + c * 4);
            }
        }

        // compute: 2 k8-steps
#pragma unroll
        for (int kk = 0; kk < 2; kk++) {
            int kb = kk * 8 + (lane & 3);
            int rb0 = warpM * 64 + (lane >> 2);
            int cb0 = warpN * 64 + (lane >> 2);
            unsigned af[4][4], bf[8][2];
#pragma unroll
            for (int mf = 0; mf < 4; mf++) {
                int r = rb0 + mf * 16;
                af[mf][0] = __float_as_uint(As[cur][r    ][kb    ]);
                af[mf][1] = __float_as_uint(As[cur][r + 8][kb    ]);
                af[mf][2] = __float_as_uint(As[cur][r    ][kb + 4]);
                af[mf][3] = __float_as_uint(As[cur][r + 8][kb + 4]);
            }
#pragma unroll
            for (int nf = 0; nf < 8; nf++) {
                int n = cb0 + nf * 8;
                bf[nf][0] = __float_as_uint(Bs[cur][n][kb    ]);
                bf[nf][1] = __float_as_uint(Bs[cur][n][kb + 4]);
            }
#pragma unroll
            for (int mf = 0; mf < 4; mf++)
#pragma unroll
                for (int nf = 0; nf < 8; nf++) {
                    asm volatile(
                        "mma.sync.aligned.m16n8k8.row.col.f32.tf32.tf32.f32 "
                        "{%0,%1,%2,%3}, {%4,%5,%6,%7}, {%8,%9}, {%0,%1,%2,%3};"
                        : "+f"(acc[mf][nf][0]), "+f"(acc[mf][nf][1]),
                          "+f"(acc[mf][nf][2]), "+f"(acc[mf][nf][3])
                        : "r"(af[mf][0]), "r"(af[mf][1]),
                          "r"(af[mf][2]), "r"(af[mf][3]),
                          "r"(bf[nf][0]), "r"(bf[nf][1]));
                }
        }

        // store prefetched tile into the other buffer
        if (kt < NKT - 1) {
            float* ar = &As[cur ^ 1][tid][0];
            float* br = &Bs[cur ^ 1][tid][0];
#pragma unroll
            for (int c = 0; c < 4; c++) {
                ar[c*4+0] = __uint_as_float(f2tf32(ra[c].x));
                ar[c*4+1] = __uint_as_float(f2tf32(ra[c].y));
                ar[c*4+2] = __uint_as_float(f2tf32(ra[c].z));
                ar[c*4+3] = __uint_as_float(f2tf32(ra[c].w));
                br[c*4+0] = __uint_as_float(f2tf32(rb[c].x));
                br[c*4+1] = __uint_as_float(f2tf32(rb[c].y));
                br[c*4+2] = __uint_as_float(f2tf32(rb[c].z));
                br[c*4+3] = __uint_as_float(f2tf32(rb[c].w));
            }
            __syncthreads();
        }
    }

    // epilogue
    int g = lane >> 2, t = lane & 3;
#pragma unroll
    for (int mf = 0; mf < 4; mf++) {
#pragma unroll
        for (int half = 0; half < 2; half++) {
            int m = m0 + warpM * 64 + mf * 16 + g + half * 8;
#pragma unroll
            for (int nf = 0; nf < 8; nf++) {
                int n = n0 + warpN * 64 + nf * 8 + t * 2;
                float v0 = acc[mf][nf][half * 2 + 0];
                float v1 = acc[mf][nf][half * 2 + 1];
                if (mode == 0) {
                    int b = m >> 11, s = m & (SEQ - 1);
                    int h = n >> 7,  d = n & (HD - 1);
                    float* dst = &C[(((size_t)(b * NH + h)) * SEQ + s) * HD + d];
                    dst[0] = v0; dst[1] = v1;   // d, d+1 same head (n0%128==0, step 2)
                } else {
                    float* dst = &C[(size_t)m * DM + n];
                    dst[0] = v0; dst[1] = v1;
                }
            }
        }
    }
}

// ---------------- RoPE tables ----------------
__global__ void rope_table_kernel() {
    int idx = blockIdx.x * 256 + threadIdx.x;   // SEQ*64
    if (idx >= SEQ * 64) return;
    int s = idx >> 6, i = idx & 63;
    float inv = (float)pow(10000.0, -(double)(2 * i) / 128.0);
    float ang = (float)s * inv;
    g_cos[idx] = cosf(ang);
    g_sin[idx] = sinf(ang);
}

// ---------------- RoPE apply (in place on g_q / g_k) ----------------
__global__ void rope_apply_kernel() {
    int idx = blockIdx.x * 256 + threadIdx.x;   // 32*2048*64 elements
    float* t = blockIdx.y ? g_k : g_q;
    int i = idx & 63;
    int s = (idx >> 6) & (SEQ - 1);
    float c  = g_cos[s * 64 + i];
    float sn = g_sin[s * 64 + i];
    size_t base = ((size_t)(idx >> 6)) * HD;    // (bh*SEQ + s)*128
    float a = t[base + i];
    float b = t[base + 64 + i];
    t[base + i]      = a * c - b * sn;
    t[base + 64 + i] = b * c + a * sn;
}

// ---------------- flash attention (fp32, causal, online softmax) ----------------
#define FBM 64
#define FBN 64
#define FLASH_SMEM ((128*64 + 128*64 + 64*65 + 3*64) * 4)

__global__ __launch_bounds__(256) void flash_kernel()
{
    extern __shared__ float sm[];
    float* Qs    = sm;                  // [128][64]  (d-major, Q pre-scaled)
    float* KVs   = sm + 128 * 64;       // K: [128][64] then V: [64][128]
    float* Ps    = KVs + 128 * 64;      // [64][65]
    float* rowm  = Ps + 64 * 65;
    float* rowl  = rowm + 64;
    float* rowsc = rowl + 64;

    int tid = threadIdx.x;
    int qb  = blockIdx.x;
    int bh  = blockIdx.y;

    const float* Qg = g_q + (size_t)bh * SEQ * HD;
    const float* Kg = g_k + (size_t)bh * SEQ * HD;
    const float* Vg = g_v + (size_t)bh * SEQ * HD;

    int lr  = tid >> 2;
    int lcb = (tid & 3) * 32;

    const float qscale = 0.08838834764831845f;
#pragma unroll
    for (int c = 0; c < 32; c += 4) {
        float4 v = *(const float4*)(Qg + (size_t)(qb * FBM + lr) * HD + lcb + c);
        Qs[(lcb + c + 0) * 64 + lr] = v.x * qscale;
        Qs[(lcb + c + 1) * 64 + lr] = v.y * qscale;
        Qs[(lcb + c + 2) * 64 + lr] = v.z * qscale;
        Qs[(lcb + c + 3) * 64 + lr] = v.w * qscale;
    }
    if (tid < 64) { rowm[tid] = -1e30f; rowl[tid] = 0.f; }

    int tx = tid & 15, ty = tid >> 4;
    float O[4][8];
#pragma unroll
    for (int i = 0; i < 4; i++)
#pragma unroll
        for (int j = 0; j < 8; j++) O[i][j] = 0.f;

    for (int kb = 0; kb <= qb; kb++) {
        __syncthreads();
#pragma unroll
        for (int c = 0; c < 32; c += 4) {
            float4 v = *(const float4*)(Kg + (size_t)(kb * FBN + lr) * HD + lcb + c);
            KVs[(lcb + c + 0) * 64 + lr] = v.x;
            KVs[(lcb + c + 1) * 64 + lr] = v.y;
            KVs[(lcb + c + 2) * 64 + lr] = v.z;
            KVs[(lcb + c + 3) * 64 + lr] = v.w;
        }
        __syncthreads();

        float s[4][4];
#pragma unroll
        for (int i = 0; i < 4; i++)
#pragma unroll
            for (int j = 0; j < 4; j++) s[i][j] = 0.f;
#pragma unroll 4
        for (int d = 0; d < HD; d++) {
            float4 q4 = *(const float4*)&Qs [d * 64 + ty * 4];
            float4 k4 = *(const float4*)&KVs[d * 64 + tx * 4];
            float qv[4] = {q4.x, q4.y, q4.z, q4.w};
            float kv[4] = {k4.x, k4.y, k4.z, k4.w};
#pragma unroll
            for (int i = 0; i < 4; i++)
#pragma unroll
                for (int j = 0; j < 4; j++) s[i][j] += qv[i] * kv[j];
        }
        if (kb == qb) {
#pragma unroll
            for (int i = 0; i < 4; i++)
#pragma unroll
                for (int j = 0; j < 4; j++)
                    if ((tx * 4 + j) > (ty * 4 + i)) s[i][j] = -1e30f;
        }
#pragma unroll
        for (int i = 0; i < 4; i++)
#pragma unroll
            for (int j = 0; j < 4; j++)
                Ps[(ty * 4 + i) * 65 + tx * 4 + j] = s[i][j];
        __syncthreads();

        if (tid < 64) {
            int r = tid;
            float mold = rowm[r];
            float mx = mold;
#pragma unroll 8
            for (int c = 0; c < 64; c++) mx = fmaxf(mx, Ps[r * 65 + c]);
            float sc = __expf(mold - mx);
            float sum = 0.f;
#pragma unroll 8
            for (int c = 0; c < 64; c++) {
                float p = __expf(Ps[r * 65 + c] - mx);
                Ps[r * 65 + c] = p;
                sum += p;
            }
            rowl[r]  = rowl[r] * sc + sum;
            rowm[r]  = mx;
            rowsc[r] = sc;
        }
        __syncthreads();

#pragma unroll
        for (int i = 0; i < 4; i++) {
            float sc = rowsc[ty * 4 + i];
#pragma unroll
            for (int j = 0; j < 8; j++) O[i][j] *= sc;
        }
#pragma unroll
        for (int c = 0; c < 32; c += 4) {
            float4 v = *(const float4*)(Vg + (size_t)(kb * FBN + lr) * HD + lcb + c);
            *(float4*)&KVs[lr * HD + lcb + c] = v;
        }
        __syncthreads();

#pragma unroll 2
        for (int j = 0; j < FBN; j++) {
            float4 v0 = *(const float4*)&KVs[j * HD + tx * 8];
            float4 v1 = *(const float4*)&KVs[j * HD + tx * 8 + 4];
            float vv[8] = {v0.x, v0.y, v0.z, v0.w, v1.x, v1.y, v1.z, v1.w};
#pragma unroll
            for (int i = 0; i < 4; i++) {
                float p = Ps[(ty * 4 + i) * 65 + j];
#pragma unroll
                for (int c = 0; c < 8; c++) O[i][c] += p * vv[c];
            }
        }
    }

    int b = bh >> 4, h = bh & 15;
#pragma unroll
    for (int i = 0; i < 4; i++) {
        int r = ty * 4 + i;
        float inv = 1.0f / rowl[r];
        int srow = qb * FBM + r;
        float* dst = g_ctx + ((size_t)(b * SEQ + srow)) * DM + h * HD + tx * 8;
#pragma unroll
        for (int c = 0; c < 8; c++) dst[c] = O[i][c] * inv;
    }
}

// ---------------- launcher ----------------
extern "C" void kernel_launch(void* const* d_in, const int* in_sizes, int n_in,
                              void* d_out, int out_size)
{
    const float* x  = (const float*)d_in[0];
    const float* Wq = (const float*)d_in[1];
    const float* Wk = (const float*)d_in[2];
    const float* Wv = (const float*)d_in[3];
    const float* Wo = (const float*)d_in[4];
    float* out = (float*)d_out;

    cudaFuncSetAttribute(flash_kernel,
                         cudaFuncAttributeMaxDynamicSharedMemorySize, FLASH_SMEM);

    // Q/K/V projections -> head layout (TF32 tensor cores)
    gemm_tc_kernel<<<dim3(DM/128, MT/128, 3), 128>>>(x, Wq, Wk, Wv, nullptr, 0);
    // RoPE tables + apply to Q and K
    rope_table_kernel<<<(SEQ*64)/256, 256>>>();
    rope_apply_kernel<<<dim3((NB*NH*SEQ*64)/256, 2), 256>>>();
    // causal flash attention -> g_ctx
    flash_kernel<<<dim3(SEQ/FBM, NB*NH), 256, FLASH_SMEM>>>();
    // output projection (TF32 tensor cores)
    gemm_tc_kernel<<<dim3(DM/128, MT/128, 1), 128>>>(nullptr, Wo, nullptr, nullptr, out, 1);
}

// round 7
// speedup vs baseline: 1.9673x; 1.4390x over previous
#include <cuda_runtime.h>
#include <math.h>
#include <stdint.h>

#define SEQ   2048
#define DM    2048
#define NH    16
#define HD    128
#define NB    2
#define MT    (NB*SEQ)          // 4096 rows

// ---------------- scratch (static __device__, no allocs) ----------------
__device__ float g_q  [NB*NH*SEQ*HD];   // [b][h][s][d]
__device__ float g_k  [NB*NH*SEQ*HD];
__device__ float g_v  [NB*NH*SEQ*HD];
__device__ float g_ctx[(size_t)MT*DM];  // [b*s][D]
__device__ float g_cos[SEQ*64];
__device__ float g_sin[SEQ*64];

__device__ __forceinline__ unsigned f2tf32(float x) {
    unsigned r;
    asm("cvt.rna.tf32.f32 %0, %1;" : "=r"(r) : "f"(x));
    return r;
}
__device__ __forceinline__ float tf32f(float x) {
    return __uint_as_float(f2tf32(x));
}

// ---------------- TF32 tensor-core GEMM: C = A[M,K] * W[N,K]^T ----------------
// (unchanged from the passing round-3 kernel)
#define KSTRIDE 20

__global__ __launch_bounds__(128) void gemm_tc_kernel(
    const float* __restrict__ Ap, const float* __restrict__ W0,
    const float* __restrict__ W1, const float* __restrict__ W2,
    float* __restrict__ outp, int mode)
{
    __shared__ float As[2][128][KSTRIDE];
    __shared__ float Bs[2][128][KSTRIDE];

    const float* A;
    const float* W;
    float* C;
    int z = blockIdx.z;
    if (mode == 0) {
        A = Ap;
        W = (z == 0) ? W0 : (z == 1) ? W1 : W2;
        C = (z == 0) ? g_q : (z == 1) ? g_k : g_v;
    } else {
        A = g_ctx; W = W0; C = outp;
    }

    int tid   = threadIdx.x;
    int lane  = tid & 31;
    int warp  = tid >> 5;
    int warpM = warp >> 1;
    int warpN = warp & 1;
    int m0    = blockIdx.y * 128;
    int n0    = blockIdx.x * 128;

    const float* Ag = A + (size_t)(m0 + tid) * DM;
    const float* Wg = W + (size_t)(n0 + tid) * DM;

    float acc[4][8][4];
#pragma unroll
    for (int i = 0; i < 4; i++)
#pragma unroll
        for (int j = 0; j < 8; j++)
#pragma unroll
            for (int c = 0; c < 4; c++) acc[i][j][c] = 0.f;

    float4 ra[4], rb[4];
#pragma unroll
    for (int c = 0; c < 4; c++) {
        ra[c] = *(const float4*)(Ag + c * 4);
        rb[c] = *(const float4*)(Wg + c * 4);
    }
    {
        float* ar = &As[0][tid][0];
        float* br = &Bs[0][tid][0];
#pragma unroll
        for (int c = 0; c < 4; c++) {
            ar[c*4+0] = tf32f(ra[c].x); ar[c*4+1] = tf32f(ra[c].y);
            ar[c*4+2] = tf32f(ra[c].z); ar[c*4+3] = tf32f(ra[c].w);
            br[c*4+0] = tf32f(rb[c].x); br[c*4+1] = tf32f(rb[c].y);
            br[c*4+2] = tf32f(rb[c].z); br[c*4+3] = tf32f(rb[c].w);
        }
    }
    __syncthreads();

    const int NKT = DM / 16;
    for (int kt = 0; kt < NKT; kt++) {
        int cur = kt & 1;
        if (kt < NKT - 1) {
            const float* ap = Ag + (kt + 1) * 16;
            const float* wp = Wg + (kt + 1) * 16;
#pragma unroll
            for (int c = 0; c < 4; c++) {
                ra[c] = *(const float4*)(ap + c * 4);
                rb[c] = *(const float4*)(wp + c * 4);
            }
        }

#pragma unroll
        for (int kk = 0; kk < 2; kk++) {
            int kb = kk * 8 + (lane & 3);
            int rb0 = warpM * 64 + (lane >> 2);
            int cb0 = warpN * 64 + (lane >> 2);
            unsigned af[4][4], bf[8][2];
#pragma unroll
            for (int mf = 0; mf < 4; mf++) {
                int r = rb0 + mf * 16;
                af[mf][0] = __float_as_uint(As[cur][r    ][kb    ]);
                af[mf][1] = __float_as_uint(As[cur][r + 8][kb    ]);
                af[mf][2] = __float_as_uint(As[cur][r    ][kb + 4]);
                af[mf][3] = __float_as_uint(As[cur][r + 8][kb + 4]);
            }
#pragma unroll
            for (int nf = 0; nf < 8; nf++) {
                int n = cb0 + nf * 8;
                bf[nf][0] = __float_as_uint(Bs[cur][n][kb    ]);
                bf[nf][1] = __float_as_uint(Bs[cur][n][kb + 4]);
            }
#pragma unroll
            for (int mf = 0; mf < 4; mf++)
#pragma unroll
                for (int nf = 0; nf < 8; nf++) {
                    asm volatile(
                        "mma.sync.aligned.m16n8k8.row.col.f32.tf32.tf32.f32 "
                        "{%0,%1,%2,%3}, {%4,%5,%6,%7}, {%8,%9}, {%0,%1,%2,%3};"
                        : "+f"(acc[mf][nf][0]), "+f"(acc[mf][nf][1]),
                          "+f"(acc[mf][nf][2]), "+f"(acc[mf][nf][3])
                        : "r"(af[mf][0]), "r"(af[mf][1]),
                          "r"(af[mf][2]), "r"(af[mf][3]),
                          "r"(bf[nf][0]), "r"(bf[nf][1]));
                }
        }

        if (kt < NKT - 1) {
            float* ar = &As[cur ^ 1][tid][0];
            float* br = &Bs[cur ^ 1][tid][0];
#pragma unroll
            for (int c = 0; c < 4; c++) {
                ar[c*4+0] = tf32f(ra[c].x); ar[c*4+1] = tf32f(ra[c].y);
                ar[c*4+2] = tf32f(ra[c].z); ar[c*4+3] = tf32f(ra[c].w);
                br[c*4+0] = tf32f(rb[c].x); br[c*4+1] = tf32f(rb[c].y);
                br[c*4+2] = tf32f(rb[c].z); br[c*4+3] = tf32f(rb[c].w);
            }
            __syncthreads();
        }
    }

    int g = lane >> 2, t = lane & 3;
#pragma unroll
    for (int mf = 0; mf < 4; mf++) {
#pragma unroll
        for (int half = 0; half < 2; half++) {
            int m = m0 + warpM * 64 + mf * 16 + g + half * 8;
#pragma unroll
            for (int nf = 0; nf < 8; nf++) {
                int n = n0 + warpN * 64 + nf * 8 + t * 2;
                float v0 = acc[mf][nf][half * 2 + 0];
                float v1 = acc[mf][nf][half * 2 + 1];
                if (mode == 0) {
                    int b = m >> 11, s = m & (SEQ - 1);
                    int h = n >> 7,  d = n & (HD - 1);
                    float* dst = &C[(((size_t)(b * NH + h)) * SEQ + s) * HD + d];
                    dst[0] = v0; dst[1] = v1;
                } else {
                    float* dst = &C[(size_t)m * DM + n];
                    dst[0] = v0; dst[1] = v1;
                }
            }
        }
    }
}

// ---------------- RoPE ----------------
__global__ void rope_table_kernel() {
    int idx = blockIdx.x * 256 + threadIdx.x;
    if (idx >= SEQ * 64) return;
    int s = idx >> 6, i = idx & 63;
    float inv = (float)pow(10000.0, -(double)(2 * i) / 128.0);
    float ang = (float)s * inv;
    g_cos[idx] = cosf(ang);
    g_sin[idx] = sinf(ang);
}

__global__ void rope_apply_kernel() {
    int idx = blockIdx.x * 256 + threadIdx.x;
    float* t = blockIdx.y ? g_k : g_q;
    int i = idx & 63;
    int s = (idx >> 6) & (SEQ - 1);
    float c  = g_cos[s * 64 + i];
    float sn = g_sin[s * 64 + i];
    size_t base = ((size_t)(idx >> 6)) * HD;
    float a = t[base + i];
    float b = t[base + 64 + i];
    t[base + i]      = a * c - b * sn;
    t[base + 64 + i] = b * c + a * sn;
}

// ---------------- TF32 tensor-core flash attention ----------------
// q-tile 128 (8 warps x 16 rows), kv-tile 64, causal, warp-local softmax.
// Q A-fragments register-resident; K^T / V / P in smem (conflict-free strides).
#define QB 128
#define KVB 64
#define KS_STRIDE 68     // Ks[d][kv]: 128 x 68
#define VS_STRIDE 132    // Vs[kv][d]: 64 x 132
#define PS_STRIDE 68     // Ps[q][kv]: 128 x 68
#define F_SMEM ((128*KS_STRIDE + KVB*VS_STRIDE + 128*PS_STRIDE) * 4)

__global__ __launch_bounds__(256, 1) void flash_tc_kernel()
{
    extern __shared__ float sm[];
    float* Ks = sm;                              // [128][68]
    float* Vs = Ks + 128 * KS_STRIDE;            // [64][132]
    float* Ps = Vs + KVB * VS_STRIDE;            // [128][68]

    int tid  = threadIdx.x;
    int lane = tid & 31;
    int w    = tid >> 5;            // 0..7
    int qb   = blockIdx.x;          // 0..15
    int bh   = blockIdx.y;          // 0..31

    const float* Qg = g_q + (size_t)bh * SEQ * HD;
    const float* Kg = g_k + (size_t)bh * SEQ * HD;
    const float* Vg = g_v + (size_t)bh * SEQ * HD;

    int g = lane >> 2;              // 0..7
    int t4 = lane & 3;              // 0..3

    // ---- load Q fragments to registers (row-major A, m16n8k8) ----
    const float qscale = 0.08838834764831845f;   // 1/sqrt(128)
    int r0 = qb * QB + w * 16 + g;               // global q row (lane part)
    unsigned qf[16][4];
#pragma unroll
    for (int ks = 0; ks < 16; ks++) {
        int k = ks * 8 + t4;
        qf[ks][0] = f2tf32(Qg[(size_t)r0       * HD + k    ] * qscale);
        qf[ks][1] = f2tf32(Qg[(size_t)(r0 + 8) * HD + k    ] * qscale);
        qf[ks][2] = f2tf32(Qg[(size_t)r0       * HD + k + 4] * qscale);
        qf[ks][3] = f2tf32(Qg[(size_t)(r0 + 8) * HD + k + 4] * qscale);
    }

    float o[16][4];
#pragma unroll
    for (int nf = 0; nf < 16; nf++)
#pragma unroll
        for (int c = 0; c < 4; c++) o[nf][c] = 0.f;
    float m0 = -1e30f, m1 = -1e30f, l0 = 0.f, l1 = 0.f;

    int nblocks = 2 * qb + 2;
    for (int j = 0; j < nblocks; j++) {
        __syncthreads();   // all warps done reading Ks/Vs from prev iter

        // ---- load K (transposed, tf32) and V (natural, tf32) ----
        {
            int kv = tid >> 2;               // 0..63
            int dbase = (tid & 3) * 32;
            const float* krow = Kg + (size_t)(j * KVB + kv) * HD + dbase;
            const float* vrow = Vg + (size_t)(j * KVB + kv) * HD + dbase;
#pragma unroll
            for (int c = 0; c < 8; c++) {
                float4 kvv = *(const float4*)(krow + c * 4);
                int d = dbase + c * 4;
                Ks[(d + 0) * KS_STRIDE + kv] = tf32f(kvv.x);
                Ks[(d + 1) * KS_STRIDE + kv] = tf32f(kvv.y);
                Ks[(d + 2) * KS_STRIDE + kv] = tf32f(kvv.z);
                Ks[(d + 3) * KS_STRIDE + kv] = tf32f(kvv.w);
                float4 vv = *(const float4*)(vrow + c * 4);
                vv.x = tf32f(vv.x); vv.y = tf32f(vv.y);
                vv.z = tf32f(vv.z); vv.w = tf32f(vv.w);
                *(float4*)&Vs[kv * VS_STRIDE + d] = vv;
            }
        }
        __syncthreads();

        // ---- S = Q K^T  (warp: 16 rows x 64 cols) ----
        float s[8][4];
#pragma unroll
        for (int nf = 0; nf < 8; nf++)
#pragma unroll
            for (int c = 0; c < 4; c++) s[nf][c] = 0.f;
#pragma unroll
        for (int ks = 0; ks < 16; ks++) {
            int krow = ks * 8 + t4;
#pragma unroll
            for (int nf = 0; nf < 8; nf++) {
                unsigned b0 = __float_as_uint(Ks[krow       * KS_STRIDE + nf * 8 + g]);
                unsigned b1 = __float_as_uint(Ks[(krow + 4) * KS_STRIDE + nf * 8 + g]);
                asm volatile(
                    "mma.sync.aligned.m16n8k8.row.col.f32.tf32.tf32.f32 "
                    "{%0,%1,%2,%3}, {%4,%5,%6,%7}, {%8,%9}, {%0,%1,%2,%3};"
                    : "+f"(s[nf][0]), "+f"(s[nf][1]), "+f"(s[nf][2]), "+f"(s[nf][3])
                    : "r"(qf[ks][0]), "r"(qf[ks][1]), "r"(qf[ks][2]), "r"(qf[ks][3]),
                      "r"(b0), "r"(b1));
            }
        }

        // ---- causal mask (only last two blocks need it) ----
        if (j >= 2 * qb) {
            int rg0 = qb * QB + w * 16 + g;
            int rg1 = rg0 + 8;
#pragma unroll
            for (int nf = 0; nf < 8; nf++) {
                int cg = j * KVB + nf * 8 + t4 * 2;
                if (cg     > rg0) s[nf][0] = -1e30f;
                if (cg + 1 > rg0) s[nf][1] = -1e30f;
                if (cg     > rg1) s[nf][2] = -1e30f;
                if (cg + 1 > rg1) s[nf][3] = -1e30f;
            }
        }

        // ---- warp-local online softmax ----
        float mx0 = -1e30f, mx1 = -1e30f;
#pragma unroll
        for (int nf = 0; nf < 8; nf++) {
            mx0 = fmaxf(mx0, fmaxf(s[nf][0], s[nf][1]));
            mx1 = fmaxf(mx1, fmaxf(s[nf][2], s[nf][3]));
        }
        mx0 = fmaxf(mx0, __shfl_xor_sync(0xFFFFFFFF, mx0, 1));
        mx0 = fmaxf(mx0, __shfl_xor_sync(0xFFFFFFFF, mx0, 2));
        mx1 = fmaxf(mx1, __shfl_xor_sync(0xFFFFFFFF, mx1, 1));
        mx1 = fmaxf(mx1, __shfl_xor_sync(0xFFFFFFFF, mx1, 2));

        float m0n = fmaxf(m0, mx0), m1n = fmaxf(m1, mx1);
        float sc0 = __expf(m0 - m0n), sc1 = __expf(m1 - m1n);

        float sum0 = 0.f, sum1 = 0.f;
        int rl = w * 16 + g;
#pragma unroll
        for (int nf = 0; nf < 8; nf++) {
            float p0 = __expf(s[nf][0] - m0n);
            float p1 = __expf(s[nf][1] - m0n);
            float p2 = __expf(s[nf][2] - m1n);
            float p3 = __expf(s[nf][3] - m1n);
            sum0 += p0 + p1;
            sum1 += p2 + p3;
            int c = nf * 8 + t4 * 2;
            Ps[rl       * PS_STRIDE + c    ] = tf32f(p0);
            Ps[rl       * PS_STRIDE + c + 1] = tf32f(p1);
            Ps[(rl + 8) * PS_STRIDE + c    ] = tf32f(p2);
            Ps[(rl + 8) * PS_STRIDE + c + 1] = tf32f(p3);
        }
        sum0 += __shfl_xor_sync(0xFFFFFFFF, sum0, 1);
        sum0 += __shfl_xor_sync(0xFFFFFFFF, sum0, 2);
        sum1 += __shfl_xor_sync(0xFFFFFFFF, sum1, 1);
        sum1 += __shfl_xor_sync(0xFFFFFFFF, sum1, 2);

        l0 = l0 * sc0 + sum0;  m0 = m0n;
        l1 = l1 * sc1 + sum1;  m1 = m1n;
#pragma unroll
        for (int nf = 0; nf < 16; nf++) {
            o[nf][0] *= sc0; o[nf][1] *= sc0;
            o[nf][2] *= sc1; o[nf][3] *= sc1;
        }
        __syncwarp();   // Ps rows are warp-private; make stores visible to lanes

        // ---- O += P V  (warp: 16 rows x 128 cols) ----
#pragma unroll
        for (int ks2 = 0; ks2 < 8; ks2++) {
            int kk = ks2 * 8 + t4;
            unsigned pa0 = __float_as_uint(Ps[rl       * PS_STRIDE + kk    ]);
            unsigned pa1 = __float_as_uint(Ps[(rl + 8) * PS_STRIDE + kk    ]);
            unsigned pa2 = __float_as_uint(Ps[rl       * PS_STRIDE + kk + 4]);
            unsigned pa3 = __float_as_uint(Ps[(rl + 8) * PS_STRIDE + kk + 4]);
#pragma unroll
            for (int nf = 0; nf < 16; nf++) {
                unsigned b0 = __float_as_uint(Vs[(ks2 * 8 + t4)     * VS_STRIDE + nf * 8 + g]);
                unsigned b1 = __float_as_uint(Vs[(ks2 * 8 + t4 + 4) * VS_STRIDE + nf * 8 + g]);
                asm volatile(
                    "mma.sync.aligned.m16n8k8.row.col.f32.tf32.tf32.f32 "
                    "{%0,%1,%2,%3}, {%4,%5,%6,%7}, {%8,%9}, {%0,%1,%2,%3};"
                    : "+f"(o[nf][0]), "+f"(o[nf][1]), "+f"(o[nf][2]), "+f"(o[nf][3])
                    : "r"(pa0), "r"(pa1), "r"(pa2), "r"(pa3),
                      "r"(b0), "r"(b1));
            }
        }
    }

    // ---- epilogue: O /= l, write ctx [b][s][h*128+d] ----
    float inv0 = 1.0f / l0, inv1 = 1.0f / l1;
    int b = bh >> 4, h = bh & 15;
    int srow0 = qb * QB + w * 16 + g;
#pragma unroll
    for (int nf = 0; nf < 16; nf++) {
        int d = nf * 8 + t4 * 2;
        float* d0 = g_ctx + ((size_t)(b * SEQ + srow0)) * DM + h * HD + d;
        float* d1 = g_ctx + ((size_t)(b * SEQ + srow0 + 8)) * DM + h * HD + d;
        d0[0] = o[nf][0] * inv0; d0[1] = o[nf][1] * inv0;
        d1[0] = o[nf][2] * inv1; d1[1] = o[nf][3] * inv1;
    }
}

// ---------------- launcher ----------------
extern "C" void kernel_launch(void* const* d_in, const int* in_sizes, int n_in,
                              void* d_out, int out_size)
{
    const float* x  = (const float*)d_in[0];
    const float* Wq = (const float*)d_in[1];
    const float* Wk = (const float*)d_in[2];
    const float* Wv = (const float*)d_in[3];
    const float* Wo = (const float*)d_in[4];
    float* out = (float*)d_out;

    cudaFuncSetAttribute(flash_tc_kernel,
                         cudaFuncAttributeMaxDynamicSharedMemorySize, F_SMEM);

    // Q/K/V projections (TF32 tensor cores) -> head layout
    gemm_tc_kernel<<<dim3(DM/128, MT/128, 3), 128>>>(x, Wq, Wk, Wv, nullptr, 0);
    // RoPE
    rope_table_kernel<<<(SEQ*64)/256, 256>>>();
    rope_apply_kernel<<<dim3((NB*NH*SEQ*64)/256, 2), 256>>>();
    // causal flash attention (TF32 tensor cores) -> g_ctx
    flash_tc_kernel<<<dim3(SEQ/QB, NB*NH), 256, F_SMEM>>>();
    // output projection
    gemm_tc_kernel<<<dim3(DM/128, MT/128, 1), 128>>>(nullptr, Wo, nullptr, nullptr, out, 1);
}

// round 11
// speedup vs baseline: 2.3746x; 1.2070x over previous
#include <cuda_runtime.h>
#include <math.h>
#include <stdint.h>

#define SEQ   2048
#define DM    2048
#define NH    16
#define HD    128
#define NB    2
#define MT    (NB*SEQ)          // 4096 rows

// ---------------- scratch (static __device__, no allocs) ----------------
__device__ float g_q  [NB*NH*SEQ*HD];   // [b][h][s][d]
__device__ float g_k  [NB*NH*SEQ*HD];
__device__ float g_v  [NB*NH*SEQ*HD];
__device__ float g_ctx[(size_t)MT*DM];  // [b*s][D]
__device__ float g_cos[SEQ*64];
__device__ float g_sin[SEQ*64];

__device__ __forceinline__ unsigned f2tf32(float x) {
    unsigned r;
    asm("cvt.rna.tf32.f32 %0, %1;" : "=r"(r) : "f"(x));
    return r;
}
__device__ __forceinline__ float tf32f(float x) {
    return __uint_as_float(f2tf32(x));
}

// ---------------- TF32 tensor-core GEMM: C = A[M,K] * W[N,K]^T ----------------
// BM=BN=128, BK=16, 256 threads (8 warps, 2x4), warp tile 64x32.
// Double-buffered smem stride 20 (conflict-free), register-prefetch pipeline.
// 2 CTAs/SM (4 warps/SMSP) for LDS latency hiding.
#define KSTRIDE 20

__global__ __launch_bounds__(256, 2) void gemm_tc_kernel(
    const float* __restrict__ Ap, const float* __restrict__ W0,
    const float* __restrict__ W1, const float* __restrict__ W2,
    float* __restrict__ outp, int mode)
{
    __shared__ float As[2][128][KSTRIDE];
    __shared__ float Bs[2][128][KSTRIDE];

    const float* A;
    const float* W;
    float* C;
    int z = blockIdx.z;
    if (mode == 0) {
        A = Ap;
        W = (z == 0) ? W0 : (z == 1) ? W1 : W2;
        C = (z == 0) ? g_q : (z == 1) ? g_k : g_v;
    } else {
        A = g_ctx; W = W0; C = outp;
    }

    int tid   = threadIdx.x;
    int lane  = tid & 31;
    int warp  = tid >> 5;
    int warpM = warp >> 2;       // 0..1
    int warpN = warp & 3;        // 0..3
    int m0    = blockIdx.y * 128;
    int n0    = blockIdx.x * 128;

    int lrow = tid >> 1;         // 0..127
    int lcol = (tid & 1) * 8;    // 0 or 8

    const float* Ag = A + (size_t)(m0 + lrow) * DM + lcol;
    const float* Wg = W + (size_t)(n0 + lrow) * DM + lcol;

    float acc[4][4][4];
#pragma unroll
    for (int i = 0; i < 4; i++)
#pragma unroll
        for (int j = 0; j < 4; j++)
#pragma unroll
            for (int c = 0; c < 4; c++) acc[i][j][c] = 0.f;

    float4 ra[2], rb[2];
    // prefetch tile 0
#pragma unroll
    for (int c = 0; c < 2; c++) {
        ra[c] = *(const float4*)(Ag + c * 4);
        rb[c] = *(const float4*)(Wg + c * 4);
    }
    {
        float* ar = &As[0][lrow][lcol];
        float* br = &Bs[0][lrow][lcol];
#pragma unroll
        for (int c = 0; c < 2; c++) {
            ar[c*4+0] = tf32f(ra[c].x); ar[c*4+1] = tf32f(ra[c].y);
            ar[c*4+2] = tf32f(ra[c].z); ar[c*4+3] = tf32f(ra[c].w);
            br[c*4+0] = tf32f(rb[c].x); br[c*4+1] = tf32f(rb[c].y);
            br[c*4+2] = tf32f(rb[c].z); br[c*4+3] = tf32f(rb[c].w);
        }
    }
    __syncthreads();

    int g = lane >> 2, t4 = lane & 3;

    const int NKT = DM / 16;
    for (int kt = 0; kt < NKT; kt++) {
        int cur = kt & 1;
        if (kt < NKT - 1) {
            const float* ap = Ag + (kt + 1) * 16;
            const float* wp = Wg + (kt + 1) * 16;
#pragma unroll
            for (int c = 0; c < 2; c++) {
                ra[c] = *(const float4*)(ap + c * 4);
                rb[c] = *(const float4*)(wp + c * 4);
            }
        }

#pragma unroll
        for (int kk = 0; kk < 2; kk++) {
            int kb  = kk * 8 + t4;
            int rb0 = warpM * 64 + g;
            int cb0 = warpN * 32 + g;
            unsigned af[4][4], bf[4][2];
#pragma unroll
            for (int mf = 0; mf < 4; mf++) {
                int r = rb0 + mf * 16;
                af[mf][0] = __float_as_uint(As[cur][r    ][kb    ]);
                af[mf][1] = __float_as_uint(As[cur][r + 8][kb    ]);
                af[mf][2] = __float_as_uint(As[cur][r    ][kb + 4]);
                af[mf][3] = __float_as_uint(As[cur][r + 8][kb + 4]);
            }
#pragma unroll
            for (int nf = 0; nf < 4; nf++) {
                int n = cb0 + nf * 8;
                bf[nf][0] = __float_as_uint(Bs[cur][n][kb    ]);
                bf[nf][1] = __float_as_uint(Bs[cur][n][kb + 4]);
            }
#pragma unroll
            for (int mf = 0; mf < 4; mf++)
#pragma unroll
                for (int nf = 0; nf < 4; nf++) {
                    asm volatile(
                        "mma.sync.aligned.m16n8k8.row.col.f32.tf32.tf32.f32 "
                        "{%0,%1,%2,%3}, {%4,%5,%6,%7}, {%8,%9}, {%0,%1,%2,%3};"
                        : "+f"(acc[mf][nf][0]), "+f"(acc[mf][nf][1]),
                          "+f"(acc[mf][nf][2]), "+f"(acc[mf][nf][3])
                        : "r"(af[mf][0]), "r"(af[mf][1]),
                          "r"(af[mf][2]), "r"(af[mf][3]),
                          "r"(bf[nf][0]), "r"(bf[nf][1]));
                }
        }

        if (kt < NKT - 1) {
            float* ar = &As[cur ^ 1][lrow][lcol];
            float* br = &Bs[cur ^ 1][lrow][lcol];
#pragma unroll
            for (int c = 0; c < 2; c++) {
                ar[c*4+0] = tf32f(ra[c].x); ar[c*4+1] = tf32f(ra[c].y);
                ar[c*4+2] = tf32f(ra[c].z); ar[c*4+3] = tf32f(ra[c].w);
                br[c*4+0] = tf32f(rb[c].x); br[c*4+1] = tf32f(rb[c].y);
                br[c*4+2] = tf32f(rb[c].z); br[c*4+3] = tf32f(rb[c].w);
            }
            __syncthreads();
        }
    }

    // epilogue
#pragma unroll
    for (int mf = 0; mf < 4; mf++) {
#pragma unroll
        for (int half = 0; half < 2; half++) {
            int m = m0 + warpM * 64 + mf * 16 + g + half * 8;
#pragma unroll
            for (int nf = 0; nf < 4; nf++) {
                int n = n0 + warpN * 32 + nf * 8 + t4 * 2;
                float v0 = acc[mf][nf][half * 2 + 0];
                float v1 = acc[mf][nf][half * 2 + 1];
                if (mode == 0) {
                    int b = m >> 11, s = m & (SEQ - 1);
                    int h = n >> 7,  d = n & (HD - 1);
                    float* dst = &C[(((size_t)(b * NH + h)) * SEQ + s) * HD + d];
                    dst[0] = v0; dst[1] = v1;
                } else {
                    float* dst = &C[(size_t)m * DM + n];
                    dst[0] = v0; dst[1] = v1;
                }
            }
        }
    }
}

// ---------------- RoPE ----------------
__global__ void rope_table_kernel() {
    int idx = blockIdx.x * 256 + threadIdx.x;
    if (idx >= SEQ * 64) return;
    int s = idx >> 6, i = idx & 63;
    float inv = (float)pow(10000.0, -(double)(2 * i) / 128.0);
    float ang = (float)s * inv;
    g_cos[idx] = cosf(ang);
    g_sin[idx] = sinf(ang);
}

__global__ void rope_apply_kernel() {
    int idx = blockIdx.x * 256 + threadIdx.x;
    float* t = blockIdx.y ? g_k : g_q;
    int i = idx & 63;
    int s = (idx >> 6) & (SEQ - 1);
    float c  = g_cos[s * 64 + i];
    float sn = g_sin[s * 64 + i];
    size_t base = ((size_t)(idx >> 6)) * HD;
    float a = t[base + i];
    float b = t[base + 64 + i];
    t[base + i]      = a * c - b * sn;
    t[base + 64 + i] = b * c + a * sn;
}

// ---------------- TF32 tensor-core flash attention ----------------
// q-tile 128 (8 warps x 16 rows), kv-tile 64, causal, warp-local softmax.
// Q A-fragments register-resident; K^T / V / P in smem (conflict-free strides).
#define QB 128
#define KVB 64
#define KS_STRIDE 68     // Ks[d][kv]: 128 x 68
#define VS_STRIDE 132    // Vs[kv][d]: 64 x 132
#define PS_STRIDE 68     // Ps[q][kv]: 128 x 68
#define F_SMEM ((128*KS_STRIDE + KVB*VS_STRIDE + 128*PS_STRIDE) * 4)

__global__ __launch_bounds__(256, 1) void flash_tc_kernel()
{
    extern __shared__ float sm[];
    float* Ks = sm;                              // [128][68]
    float* Vs = Ks + 128 * KS_STRIDE;            // [64][132]
    float* Ps = Vs + KVB * VS_STRIDE;            // [128][68]

    int tid  = threadIdx.x;
    int lane = tid & 31;
    int w    = tid >> 5;            // 0..7
    int qb   = blockIdx.x;          // 0..15
    int bh   = blockIdx.y;          // 0..31

    const float* Qg = g_q + (size_t)bh * SEQ * HD;
    const float* Kg = g_k + (size_t)bh * SEQ * HD;
    const float* Vg = g_v + (size_t)bh * SEQ * HD;

    int g = lane >> 2;              // 0..7
    int t4 = lane & 3;              // 0..3

    // ---- load Q fragments to registers (row-major A, m16n8k8) ----
    const float qscale = 0.08838834764831845f;   // 1/sqrt(128)
    int r0 = qb * QB + w * 16 + g;               // global q row (lane part)
    unsigned qf[16][4];
#pragma unroll
    for (int ks = 0; ks < 16; ks++) {
        int k = ks * 8 + t4;
        qf[ks][0] = f2tf32(Qg[(size_t)r0       * HD + k    ] * qscale);
        qf[ks][1] = f2tf32(Qg[(size_t)(r0 + 8) * HD + k    ] * qscale);
        qf[ks][2] = f2tf32(Qg[(size_t)r0       * HD + k + 4] * qscale);
        qf[ks][3] = f2tf32(Qg[(size_t)(r0 + 8) * HD + k + 4] * qscale);
    }

    float o[16][4];
#pragma unroll
    for (int nf = 0; nf < 16; nf++)
#pragma unroll
        for (int c = 0; c < 4; c++) o[nf][c] = 0.f;
    float m0 = -1e30f, m1 = -1e30f, l0 = 0.f, l1 = 0.f;

    int nblocks = 2 * qb + 2;
    for (int j = 0; j < nblocks; j++) {
        __syncthreads();   // all warps done reading Ks/Vs from prev iter

        // ---- load K (transposed, tf32) and V (natural, tf32) ----
        {
            int kv = tid >> 2;               // 0..63
            int dbase = (tid & 3) * 32;
            const float* krow = Kg + (size_t)(j * KVB + kv) * HD + dbase;
            const float* vrow = Vg + (size_t)(j * KVB + kv) * HD + dbase;
#pragma unroll
            for (int c = 0; c < 8; c++) {
                float4 kvv = *(const float4*)(krow + c * 4);
                int d = dbase + c * 4;
                Ks[(d + 0) * KS_STRIDE + kv] = tf32f(kvv.x);
                Ks[(d + 1) * KS_STRIDE + kv] = tf32f(kvv.y);
                Ks[(d + 2) * KS_STRIDE + kv] = tf32f(kvv.z);
                Ks[(d + 3) * KS_STRIDE + kv] = tf32f(kvv.w);
                float4 vv = *(const float4*)(vrow + c * 4);
                vv.x = tf32f(vv.x); vv.y = tf32f(vv.y);
                vv.z = tf32f(vv.z); vv.w = tf32f(vv.w);
                *(float4*)&Vs[kv * VS_STRIDE + d] = vv;
            }
        }
        __syncthreads();

        // ---- S = Q K^T  (warp: 16 rows x 64 cols) ----
        float s[8][4];
#pragma unroll
        for (int nf = 0; nf < 8; nf++)
#pragma unroll
            for (int c = 0; c < 4; c++) s[nf][c] = 0.f;
#pragma unroll
        for (int ks = 0; ks < 16; ks++) {
            int krow = ks * 8 + t4;
#pragma unroll
            for (int nf = 0; nf < 8; nf++) {
                unsigned b0 = __float_as_uint(Ks[krow       * KS_STRIDE + nf * 8 + g]);
                unsigned b1 = __float_as_uint(Ks[(krow + 4) * KS_STRIDE + nf * 8 + g]);
                asm volatile(
                    "mma.sync.aligned.m16n8k8.row.col.f32.tf32.tf32.f32 "
                    "{%0,%1,%2,%3}, {%4,%5,%6,%7}, {%8,%9}, {%0,%1,%2,%3};"
                    : "+f"(s[nf][0]), "+f"(s[nf][1]), "+f"(s[nf][2]), "+f"(s[nf][3])
                    : "r"(qf[ks][0]), "r"(qf[ks][1]), "r"(qf[ks][2]), "r"(qf[ks][3]),
                      "r"(b0), "r"(b1));
            }
        }

        // ---- causal mask (only last two blocks need it) ----
        if (j >= 2 * qb) {
            int rg0 = qb * QB + w * 16 + g;
            int rg1 = rg0 + 8;
#pragma unroll
            for (int nf = 0; nf < 8; nf++) {
                int cg = j * KVB + nf * 8 + t4 * 2;
                if (cg     > rg0) s[nf][0] = -1e30f;
                if (cg + 1 > rg0) s[nf][1] = -1e30f;
                if (cg     > rg1) s[nf][2] = -1e30f;
                if (cg + 1 > rg1) s[nf][3] = -1e30f;
            }
        }

        // ---- warp-local online softmax ----
        float mx0 = -1e30f, mx1 = -1e30f;
#pragma unroll
        for (int nf = 0; nf < 8; nf++) {
            mx0 = fmaxf(mx0, fmaxf(s[nf][0], s[nf][1]));
            mx1 = fmaxf(mx1, fmaxf(s[nf][2], s[nf][3]));
        }
        mx0 = fmaxf(mx0, __shfl_xor_sync(0xFFFFFFFF, mx0, 1));
        mx0 = fmaxf(mx0, __shfl_xor_sync(0xFFFFFFFF, mx0, 2));
        mx1 = fmaxf(mx1, __shfl_xor_sync(0xFFFFFFFF, mx1, 1));
        mx1 = fmaxf(mx1, __shfl_xor_sync(0xFFFFFFFF, mx1, 2));

        float m0n = fmaxf(m0, mx0), m1n = fmaxf(m1, mx1);
        float sc0 = __expf(m0 - m0n), sc1 = __expf(m1 - m1n);

        float sum0 = 0.f, sum1 = 0.f;
        int rl = w * 16 + g;
#pragma unroll
        for (int nf = 0; nf < 8; nf++) {
            float p0 = __expf(s[nf][0] - m0n);
            float p1 = __expf(s[nf][1] - m0n);
            float p2 = __expf(s[nf][2] - m1n);
            float p3 = __expf(s[nf][3] - m1n);
            sum0 += p0 + p1;
            sum1 += p2 + p3;
            int c = nf * 8 + t4 * 2;
            Ps[rl       * PS_STRIDE + c    ] = tf32f(p0);
            Ps[rl       * PS_STRIDE + c + 1] = tf32f(p1);
            Ps[(rl + 8) * PS_STRIDE + c    ] = tf32f(p2);
            Ps[(rl + 8) * PS_STRIDE + c + 1] = tf32f(p3);
        }
        sum0 += __shfl_xor_sync(0xFFFFFFFF, sum0, 1);
        sum0 += __shfl_xor_sync(0xFFFFFFFF, sum0, 2);
        sum1 += __shfl_xor_sync(0xFFFFFFFF, sum1, 1);
        sum1 += __shfl_xor_sync(0xFFFFFFFF, sum1, 2);

        l0 = l0 * sc0 + sum0;  m0 = m0n;
        l1 = l1 * sc1 + sum1;  m1 = m1n;
#pragma unroll
        for (int nf = 0; nf < 16; nf++) {
            o[nf][0] *= sc0; o[nf][1] *= sc0;
            o[nf][2] *= sc1; o[nf][3] *= sc1;
        }
        __syncwarp();   // Ps rows are warp-private; make stores visible to lanes

        // ---- O += P V  (warp: 16 rows x 128 cols) ----
#pragma unroll
        for (int ks2 = 0; ks2 < 8; ks2++) {
            int kk = ks2 * 8 + t4;
            unsigned pa0 = __float_as_uint(Ps[rl       * PS_STRIDE + kk    ]);
            unsigned pa1 = __float_as_uint(Ps[(rl + 8) * PS_STRIDE + kk    ]);
            unsigned pa2 = __float_as_uint(Ps[rl       * PS_STRIDE + kk + 4]);
            unsigned pa3 = __float_as_uint(Ps[(rl + 8) * PS_STRIDE + kk + 4]);
#pragma unroll
            for (int nf = 0; nf < 16; nf++) {
                unsigned b0 = __float_as_uint(Vs[(ks2 * 8 + t4)     * VS_STRIDE + nf * 8 + g]);
                unsigned b1 = __float_as_uint(Vs[(ks2 * 8 + t4 + 4) * VS_STRIDE + nf * 8 + g]);
                asm volatile(
                    "mma.sync.aligned.m16n8k8.row.col.f32.tf32.tf32.f32 "
                    "{%0,%1,%2,%3}, {%4,%5,%6,%7}, {%8,%9}, {%0,%1,%2,%3};"
                    : "+f"(o[nf][0]), "+f"(o[nf][1]), "+f"(o[nf][2]), "+f"(o[nf][3])
                    : "r"(pa0), "r"(pa1), "r"(pa2), "r"(pa3),
                      "r"(b0), "r"(b1));
            }
        }
    }

    // ---- epilogue: O /= l, write ctx [b][s][h*128+d] ----
    float inv0 = 1.0f / l0, inv1 = 1.0f / l1;
    int b = bh >> 4, h = bh & 15;
    int srow0 = qb * QB + w * 16 + g;
#pragma unroll
    for (int nf = 0; nf < 16; nf++) {
        int d = nf * 8 + t4 * 2;
        float* d0 = g_ctx + ((size_t)(b * SEQ + srow0)) * DM + h * HD + d;
        float* d1 = g_ctx + ((size_t)(b * SEQ + srow0 + 8)) * DM + h * HD + d;
        d0[0] = o[nf][0] * inv0; d0[1] = o[nf][1] * inv0;
        d1[0] = o[nf][2] * inv1; d1[1] = o[nf][3] * inv1;
    }
}

// ---------------- launcher ----------------
extern "C" void kernel_launch(void* const* d_in, const int* in_sizes, int n_in,
                              void* d_out, int out_size)
{
    const float* x  = (const float*)d_in[0];
    const float* Wq = (const float*)d_in[1];
    const float* Wk = (const float*)d_in[2];
    const float* Wv = (const float*)d_in[3];
    const float* Wo = (const float*)d_in[4];
    float* out = (float*)d_out;

    cudaFuncSetAttribute(flash_tc_kernel,
                         cudaFuncAttributeMaxDynamicSharedMemorySize, F_SMEM);

    // Q/K/V projections (TF32 tensor cores) -> head layout
    gemm_tc_kernel<<<dim3(DM/128, MT/128, 3), 256>>>(x, Wq, Wk, Wv, nullptr, 0);
    // RoPE
    rope_table_kernel<<<(SEQ*64)/256, 256>>>();
    rope_apply_kernel<<<dim3((NB*NH*SEQ*64)/256, 2), 256>>>();
    // causal flash attention (TF32 tensor cores) -> g_ctx
    flash_tc_kernel<<<dim3(SEQ/QB, NB*NH), 256, F_SMEM>>>();
    // output projection
    gemm_tc_kernel<<<dim3(DM/128, MT/128, 1), 256>>>(nullptr, Wo, nullptr, nullptr, out, 1);
}